// round 12
// baseline (speedup 1.0000x reference)
#include <cuda_runtime.h>
#include <cstdint>

#define Bv 256
#define Tv 512
#define Iv 128
#define Hv 256

// ---------------- scratch (device globals; no cudaMalloc allowed) ----------
// h exchange buffers, bf16x2 pairs: [buf][group][slice][row(32)][pp(8)]
// pair p (cols 2p,2p+1) stored at pp=(p&3)*2+(p>>2)  (comb for LDS.64 frags)
__device__ __align__(16) unsigned g_h0buf[2][8][16][32][8];
__device__ __align__(16) unsigned g_h1buf[2][8][16][32][8];
__device__ float g_hfinal[Bv * Hv];
__device__ unsigned g_flags0[8 * 32];               // L0 release flags
__device__ unsigned g_flags1[8 * 32];               // L1 release flags

// ---------------- helpers ---------------------------------------------------
__device__ __forceinline__ unsigned packbf(float lo, float hi) {
    unsigned r;
    asm("cvt.rn.bf16x2.f32 %0, %1, %2;" : "=r"(r) : "f"(hi), "f"(lo));
    return r;
}
__device__ __forceinline__ void mma_bf16(float c[4], unsigned a0, unsigned a1,
                                         unsigned a2, unsigned a3,
                                         unsigned b0, unsigned b1) {
    asm volatile(
        "mma.sync.aligned.m16n8k16.row.col.f32.bf16.bf16.f32 "
        "{%0,%1,%2,%3}, {%4,%5,%6,%7}, {%8,%9}, {%0,%1,%2,%3};"
        : "+f"(c[0]), "+f"(c[1]), "+f"(c[2]), "+f"(c[3])
        : "r"(a0), "r"(a1), "r"(a2), "r"(a3), "r"(b0), "r"(b1));
}
__device__ __forceinline__ float tanhfast(float x) {
    float y;
    asm("tanh.approx.f32 %0, %1;" : "=f"(y) : "f"(x));
    return y;
}
__device__ __forceinline__ float sigm(float x) {
    return fmaf(0.5f, tanhfast(0.5f * x), 0.5f);
}
__device__ __forceinline__ void pollwait(const unsigned* fp, unsigned tgt) {
    unsigned v;
    do {
        asm volatile("ld.acquire.gpu.u32 %0, [%1];" : "=r"(v) : "l"(fp));
    } while (v < tgt);
}

// ---------------- flag reset -------------------------------------------------
__global__ void resetf() {
    g_flags0[threadIdx.x] = 0u;
    g_flags1[threadIdx.x] = 0u;
}

// ---------------- fully fused 2-layer LSTM (split-release wavefront) --------
// 128 CTAs: bt (8 groups of 32 batch rows) x hs (16 H-slices of 16 cols).
// Round t = [phase L0: step t of layer 0, releases flag0 mid-round]
//           [phase L1: step t-1 of layer 1, releases flag1 at end].
// flag0 gets ~60% of a round of propagation slack; flag1 a full round.
__global__ void __launch_bounds__(256, 1) lstm_fused(
    const float* __restrict__ x, const int* __restrict__ lengths,
    const float* __restrict__ W_ih0, const float* __restrict__ W_hh0,
    const float* __restrict__ b_ih0, const float* __restrict__ b_hh0,
    const float* __restrict__ W_ih1, const float* __restrict__ W_hh1,
    const float* __restrict__ b_ih1, const float* __restrict__ b_hh1)
{
    extern __shared__ unsigned smu[];
    unsigned* W1s = smu;                   // [s32][tp8][n8][pp8]
    unsigned* W0i = smu + 16384;           // [s8][tp8][n8][pp8]
    unsigned* Hs0 = smu + 20480;           // [s16][row32][pp8]
    unsigned* Hs1 = smu + 24576;
    unsigned* Xs  = smu + 28672;           // [s8][row32][pp8]
    float (*gates0)[68] = (float(*)[68])(smu + 30720);
    float (*gates1)[68] = (float(*)[68])(smu + 32896);
    int* slen = (int*)(smu + 35072);
    int* pmax = (int*)(smu + 35104);

    int tid = threadIdx.x, lane = tid & 31, wid = tid >> 5;
    int bt = blockIdx.x & 7;
    int hs = blockIdx.x >> 3;
    int wm = wid & 1, wn = wid >> 1;       // 2(M) x 4(N=gate) warps
    int grp = lane >> 2, tig = lane & 3;
    int arow0 = wm * 16 + grp;

    // ---- W_hh0 B-fragments in registers (bf16 pairs)
    unsigned Wr0[2][16][2];
#pragma unroll
    for (int nt = 0; nt < 2; nt++) {
        int n = wn * 256 + hs * 16 + nt * 8 + grp;
        const float* p = W_hh0 + (long long)n * Hv;
#pragma unroll
        for (int s = 0; s < 16; s++) {
            Wr0[nt][s][0] = packbf(__ldg(p + s * 16 + 2 * tig),
                                   __ldg(p + s * 16 + 2 * tig + 1));
            Wr0[nt][s][1] = packbf(__ldg(p + s * 16 + 2 * tig + 8),
                                   __ldg(p + s * 16 + 2 * tig + 9));
        }
    }

    // ---- stage W1 = [W_ih1 | W_hh1] into SMEM (bf16 pairs, frag layout)
    for (int i = tid; i < 16384; i += 256) {
        int s = i >> 9, tp = (i >> 6) & 7, n = (i >> 3) & 7, pp = i & 7;
        int p = (pp >> 1) + ((pp & 1) << 2);
        int R = (tp >> 1) * 256 + hs * 16 + ((tp & 1) << 3) + n;
        int k = s * 16 + 2 * p;
        float lo, hi;
        if (k < 256) { lo = W_ih1[R * 256 + k]; hi = W_ih1[R * 256 + k + 1]; }
        else         { lo = W_hh1[R * 256 + k - 256]; hi = W_hh1[R * 256 + k - 255]; }
        W1s[i] = packbf(lo, hi);
    }
    // ---- stage W_ih0 slice into SMEM (K=128)
    for (int i = tid; i < 4096; i += 256) {
        int s = i >> 9, tp = (i >> 6) & 7, n = (i >> 3) & 7, pp = i & 7;
        int p = (pp >> 1) + ((pp & 1) << 2);
        int R = (tp >> 1) * 256 + hs * 16 + ((tp & 1) << 3) + n;
        int k = s * 16 + 2 * p;
        W0i[i] = packbf(W_ih0[R * Iv + k], W_ih0[R * Iv + k + 1]);
    }
    if (tid < 32) slen[tid] = lengths[bt * 32 + tid];
    __syncthreads();
    if (tid == 0) {
        int m = 0;
        for (int i = 0; i < 32; i++) m = max(m, slen[i]);
        pmax[0] = m;
    }
    __syncthreads();
    int maxlen = pmax[0];

    unsigned* myflag0 = g_flags0 + bt * 32 + hs;
    unsigned* myflag1 = g_flags1 + bt * 32 + hs;
    const unsigned* gflag0 = g_flags0 + bt * 32;
    const unsigned* gflag1 = g_flags1 + bt * 32;

    // accumulator-mapped biases
    float bs0[2][2], bs1[2][2];
#pragma unroll
    for (int nt = 0; nt < 2; nt++) {
        int col = wn * 256 + hs * 16 + nt * 8 + 2 * tig;
        bs0[nt][0] = b_ih0[col] + b_hh0[col];
        bs0[nt][1] = b_ih0[col + 1] + b_hh0[col + 1];
        bs1[nt][0] = b_ih1[col] + b_hh1[col];
        bs1[nt][1] = b_ih1[col + 1] + b_hh1[col + 1];
    }

    // epilogue mapping: thread owns (eb, cols 2p8, 2p8+1)
    int eb = tid >> 3, p8 = tid & 7, ej = 2 * p8;
    int pp8 = (p8 & 3) * 2 + (p8 >> 2);
    int mylen = slen[eb];
    float2 hmy0 = make_float2(0.f, 0.f), hmy1 = make_float2(0.f, 0.f);
    float2 c0 = make_float2(0.f, 0.f), c1 = make_float2(0.f, 0.f);

    // x staging mapping
    int xrow = tid >> 3;
    int xpp  = ((tid & 7) & 3) * 2 + ((tid & 7) >> 2);
    const float* xbase = x + (long long)(bt * 32 + xrow) * (Tv * Iv) + 2 * (tid & 7);

    for (int t = 0; t <= maxlen; t++) {
        // ================= PHASE L0 (layer-0 step t) =================
        // 1. x(t) LDG (latency hides under wait)
        float2 xr[8];
        if (t < maxlen) {
            const float* xp = xbase + t * Iv;
#pragma unroll
            for (int j = 0; j < 8; j++)
                xr[j] = *(const float2*)(xp + 16 * j);
        }

        // 2. wait flag0 >= t: all peers published h0(t-1)
        if (t > 0) {
            if (tid < 16) pollwait(gflag0 + tid, (unsigned)t);
        }
        __syncthreads();

        // 3. stage h0(t-1) + x(t)
        if (t > 0) {
            const uint4* s4 = (const uint4*)&g_h0buf[(t - 1) & 1][bt][0][0][0];
            uint4* d4 = (uint4*)Hs0;
#pragma unroll
            for (int i = 0; i < 4; i++) d4[tid + i * 256] = s4[tid + i * 256];
        }
        if (t < maxlen) {
#pragma unroll
            for (int j = 0; j < 8; j++)
                Xs[j * 256 + xrow * 8 + xpp] = packbf(xr[j].x, xr[j].y);
        }
        __syncthreads();

        // 4. L0 mma: gates0 = bias0 + x @ W_ih0^T + h0 @ W_hh0^T
        if (t < maxlen) {
            float acc0[2][2][4];
#pragma unroll
            for (int nt = 0; nt < 2; nt++) {
                acc0[0][nt][0] = bs0[nt][0]; acc0[0][nt][1] = bs0[nt][1];
                acc0[0][nt][2] = bs0[nt][0]; acc0[0][nt][3] = bs0[nt][1];
                acc0[1][nt][0] = 0.f; acc0[1][nt][1] = 0.f;
                acc0[1][nt][2] = 0.f; acc0[1][nt][3] = 0.f;
            }
#pragma unroll
            for (int s = 0; s < 8; s++) {
                uint2 lo = *(const uint2*)&Xs[s * 256 + arow0 * 8 + 2 * tig];
                uint2 hi = *(const uint2*)&Xs[s * 256 + (arow0 + 8) * 8 + 2 * tig];
#pragma unroll
                for (int nt = 0; nt < 2; nt++) {
                    uint2 wb = *(const uint2*)
                        &W0i[((s * 8 + wn * 2 + nt) * 8 + grp) * 8 + 2 * tig];
                    mma_bf16(acc0[s & 1][nt], lo.x, hi.x, lo.y, hi.y, wb.x, wb.y);
                }
            }
            if (t > 0) {
#pragma unroll
                for (int s = 0; s < 16; s++) {
                    uint2 lo = *(const uint2*)&Hs0[s * 256 + arow0 * 8 + 2 * tig];
                    uint2 hi = *(const uint2*)&Hs0[s * 256 + (arow0 + 8) * 8 + 2 * tig];
#pragma unroll
                    for (int nt = 0; nt < 2; nt++)
                        mma_bf16(acc0[s & 1][nt], lo.x, hi.x, lo.y, hi.y,
                                 Wr0[nt][s][0], Wr0[nt][s][1]);
                }
            }
#pragma unroll
            for (int nt = 0; nt < 2; nt++) {
                int gcl = wn * 16 + nt * 8 + 2 * tig;
                *(float2*)&gates0[arow0][gcl] = make_float2(
                    acc0[0][nt][0] + acc0[1][nt][0],
                    acc0[0][nt][1] + acc0[1][nt][1]);
                *(float2*)&gates0[arow0 + 8][gcl] = make_float2(
                    acc0[0][nt][2] + acc0[1][nt][2],
                    acc0[0][nt][3] + acc0[1][nt][3]);
            }
            __syncthreads();

            // 5. epilogue0 + publish h0(t)
            if (t < mylen) {
                float2 gi = *(const float2*)&gates0[eb][ej];
                float2 gf = *(const float2*)&gates0[eb][16 + ej];
                float2 gg = *(const float2*)&gates0[eb][32 + ej];
                float2 go = *(const float2*)&gates0[eb][48 + ej];
                float i0 = sigm(gi.x), i1 = sigm(gi.y);
                float f0 = sigm(gf.x), f1 = sigm(gf.y);
                float g0 = tanhfast(gg.x), g1 = tanhfast(gg.y);
                float o0 = sigm(go.x), o1 = sigm(go.y);
                float cn0 = fmaf(f0, c0.x, i0 * g0);
                float cn1 = fmaf(f1, c0.y, i1 * g1);
                c0 = make_float2(cn0, cn1);
                hmy0 = make_float2(o0 * tanhfast(cn0), o1 * tanhfast(cn1));
            }
            g_h0buf[t & 1][bt][hs][eb][pp8] = packbf(hmy0.x, hmy0.y);
            __syncthreads();

            // 6. EARLY release flag0 — peers get ~60% of a round of slack
            if (tid == 0) {
                unsigned nv = (unsigned)(t + 1);
                asm volatile("st.release.gpu.u32 [%0], %1;"
                             :: "l"(myflag0), "r"(nv) : "memory");
            }
        }

        // ================= PHASE L1 (layer-1 step t-1) =================
        if (t >= 1) {
            // 7. wait flag1 >= t-1 (released end of round t-2: ~free)
            if (t > 1) {
                if (tid < 16) pollwait(gflag1 + tid, (unsigned)(t - 1));
            }
            __syncthreads();

            // 8. stage h1(t-2)
            if (t > 1) {
                const uint4* s4 = (const uint4*)&g_h1buf[t & 1][bt][0][0][0];
                uint4* d4 = (uint4*)Hs1;
#pragma unroll
                for (int i = 0; i < 4; i++) d4[tid + i * 256] = s4[tid + i * 256];
            }
            __syncthreads();

            // 9. L1 mma: gates1 = bias1 + h0(t-1) @ W_ih1^T + h1(t-2) @ W_hh1^T
            float acc1[4][2][4];
#pragma unroll
            for (int nt = 0; nt < 2; nt++) {
                acc1[0][nt][0] = bs1[nt][0]; acc1[0][nt][1] = bs1[nt][1];
                acc1[0][nt][2] = bs1[nt][0]; acc1[0][nt][3] = bs1[nt][1];
#pragma unroll
                for (int ch = 1; ch < 4; ch++) {
                    acc1[ch][nt][0] = 0.f; acc1[ch][nt][1] = 0.f;
                    acc1[ch][nt][2] = 0.f; acc1[ch][nt][3] = 0.f;
                }
            }
#pragma unroll
            for (int s = 0; s < 16; s++) {
                uint2 lo = *(const uint2*)&Hs0[s * 256 + arow0 * 8 + 2 * tig];
                uint2 hi = *(const uint2*)&Hs0[s * 256 + (arow0 + 8) * 8 + 2 * tig];
#pragma unroll
                for (int nt = 0; nt < 2; nt++) {
                    uint2 wb = *(const uint2*)
                        &W1s[((s * 8 + wn * 2 + nt) * 8 + grp) * 8 + 2 * tig];
                    mma_bf16(acc1[s & 1][nt], lo.x, hi.x, lo.y, hi.y, wb.x, wb.y);
                }
            }
            if (t > 1) {
#pragma unroll
                for (int s = 0; s < 16; s++) {
                    uint2 lo = *(const uint2*)&Hs1[s * 256 + arow0 * 8 + 2 * tig];
                    uint2 hi = *(const uint2*)&Hs1[s * 256 + (arow0 + 8) * 8 + 2 * tig];
#pragma unroll
                    for (int nt = 0; nt < 2; nt++) {
                        uint2 wb = *(const uint2*)
                            &W1s[(((16 + s) * 8 + wn * 2 + nt) * 8 + grp) * 8 + 2 * tig];
                        mma_bf16(acc1[2 + (s & 1)][nt], lo.x, hi.x, lo.y, hi.y,
                                 wb.x, wb.y);
                    }
                }
            }
#pragma unroll
            for (int nt = 0; nt < 2; nt++) {
                int gcl = wn * 16 + nt * 8 + 2 * tig;
                *(float2*)&gates1[arow0][gcl] = make_float2(
                    acc1[0][nt][0] + acc1[1][nt][0] + acc1[2][nt][0] + acc1[3][nt][0],
                    acc1[0][nt][1] + acc1[1][nt][1] + acc1[2][nt][1] + acc1[3][nt][1]);
                *(float2*)&gates1[arow0 + 8][gcl] = make_float2(
                    acc1[0][nt][2] + acc1[1][nt][2] + acc1[2][nt][2] + acc1[3][nt][2],
                    acc1[0][nt][3] + acc1[1][nt][3] + acc1[2][nt][3] + acc1[3][nt][3]);
            }
            __syncthreads();

            // 10. epilogue1 + publish h1(t-1)
            if (t - 1 < mylen) {
                float2 gi = *(const float2*)&gates1[eb][ej];
                float2 gf = *(const float2*)&gates1[eb][16 + ej];
                float2 gg = *(const float2*)&gates1[eb][32 + ej];
                float2 go = *(const float2*)&gates1[eb][48 + ej];
                float i0 = sigm(gi.x), i1 = sigm(gi.y);
                float f0 = sigm(gf.x), f1 = sigm(gf.y);
                float g0 = tanhfast(gg.x), g1 = tanhfast(gg.y);
                float o0 = sigm(go.x), o1 = sigm(go.y);
                float cn0 = fmaf(f0, c1.x, i0 * g0);
                float cn1 = fmaf(f1, c1.y, i1 * g1);
                c1 = make_float2(cn0, cn1);
                hmy1 = make_float2(o0 * tanhfast(cn0), o1 * tanhfast(cn1));
            }
            g_h1buf[(t - 1) & 1][bt][hs][eb][pp8] = packbf(hmy1.x, hmy1.y);
            __syncthreads();

            // 11. release flag1 (full round of slack before it's needed)
            if (tid == 0) {
                unsigned nv = (unsigned)t;
                asm volatile("st.release.gpu.u32 [%0], %1;"
                             :: "l"(myflag1), "r"(nv) : "memory");
            }
        }
    }

    // publish final layer-1 hidden state for FC (f32)
    float* d = g_hfinal + (long long)(bt * 32 + eb) * Hv + hs * 16;
    d[ej] = hmy1.x;
    d[ej + 1] = hmy1.y;
}

// ---------------- final FC + softmax ----------------------------------------
__global__ void fc_softmax(const float* __restrict__ W_fc,
                           const float* __restrict__ b_fc, float* __restrict__ out)
{
    int b = blockIdx.x, lane = threadIdx.x;
    float logit[10];
#pragma unroll
    for (int c = 0; c < 10; c++) {
        float s = 0.0f;
        for (int h = lane; h < Hv; h += 32)
            s += g_hfinal[b * Hv + h] * W_fc[c * Hv + h];
#pragma unroll
        for (int o = 16; o; o >>= 1) s += __shfl_down_sync(0xffffffffu, s, o);
        logit[c] = s;
    }
    if (lane == 0) {
        float mx = -1e30f;
#pragma unroll
        for (int c = 0; c < 10; c++) {
            logit[c] += b_fc[c];
            mx = fmaxf(mx, logit[c]);
        }
        float sum = 0.0f;
#pragma unroll
        for (int c = 0; c < 10; c++) {
            logit[c] = expf(logit[c] - mx);
            sum += logit[c];
        }
        float inv = 1.0f / sum;
#pragma unroll
        for (int c = 0; c < 10; c++) out[b * 10 + c] = logit[c] * inv;
    }
}

// ---------------- host launcher ---------------------------------------------
extern "C" void kernel_launch(void* const* d_in, const int* in_sizes, int n_in,
                              void* d_out, int out_size)
{
    const float* x      = (const float*)d_in[0];
    const int*   length = (const int*)d_in[1];
    const float* W_fc   = (const float*)d_in[2];
    const float* b_fc   = (const float*)d_in[3];
    const float* W_ih0  = (const float*)d_in[4];
    const float* W_hh0  = (const float*)d_in[5];
    const float* b_ih0  = (const float*)d_in[6];
    const float* b_hh0  = (const float*)d_in[7];
    const float* W_ih1  = (const float*)d_in[8];
    const float* W_hh1  = (const float*)d_in[9];
    const float* b_ih1  = (const float*)d_in[10];
    const float* b_hh1  = (const float*)d_in[11];
    float* out = (float*)d_out;

    int smem = 35106 * 4;   // ~137.1 KB
    cudaFuncSetAttribute(lstm_fused, cudaFuncAttributeMaxDynamicSharedMemorySize, smem);

    // reset exchange flags (graph-replay safe)
    resetf<<<1, 256>>>();
    // fully fused 2-layer LSTM, split-release wavefront (513 rounds)
    lstm_fused<<<128, 256, smem>>>(x, length, W_ih0, W_hh0, b_ih0, b_hh0,
                                   W_ih1, W_hh1, b_ih1, b_hh1);
    // FC + softmax
    fc_softmax<<<Bv, 32>>>(W_fc, b_fc, out);
}